// round 16
// baseline (speedup 1.0000x reference)
#include <cuda_runtime.h>
#include <cuda_fp16.h>
#include <math.h>
#include <stdint.h>

// Problem constants
#define BB 4
#define NN 2048
#define CC 1024
#define HH 16
#define DD 64
#define FFD 4096
#define MROWS (BB * NN)   // 8192

// -------------------- scratch (allocation-free: __device__ globals) ---------
__device__ __half g_qkvw_h[3 * CC * CC];
__device__ __half g_projw_h[CC * CC];
__device__ __half g_w13_h[2 * FFD * CC];   // interleaved: row 2t=w1[t], 2t+1=w3[t]
__device__ __half g_w2_h[CC * FFD];

__device__ __half g_h_h[MROWS * CC];       // LN output (fp16)
__device__ __half g_qkv_h[MROWS * 3 * CC]; // qkv projection (fp16)
__device__ __half g_attn_h[MROWS * CC];    // attention output (fp16)
__device__ float  g_x1[MROWS * CC];        // x + attn_proj (fp32 residual)
__device__ __half g_b1_h[MROWS * FFD];     // silu(h@w1^T)*(h@w3^T) (fp16)

// ======================= portable PTX helpers (sm_80+) ======================
__device__ __forceinline__ uint32_t packh2(float lo, float hi) {
    __half2 h = __floats2half2_rn(lo, hi);
    return *(uint32_t*)&h;
}
__device__ __forceinline__ void cpa16(uint32_t dst, const void* src) {
    asm volatile("cp.async.ca.shared.global [%0], [%1], 16;"
                 :: "r"(dst), "l"(src));
}
#define CPA_COMMIT() asm volatile("cp.async.commit_group;" ::: "memory")
#define CPA_WAIT2()  asm volatile("cp.async.wait_group 2;" ::: "memory")
#define CPA_WAIT1()  asm volatile("cp.async.wait_group 1;" ::: "memory")

__device__ __forceinline__ void ldsm_x4(
    uint32_t& r0, uint32_t& r1, uint32_t& r2, uint32_t& r3, uint32_t addr)
{
    asm volatile("ldmatrix.sync.aligned.m8n8.x4.shared.b16 {%0,%1,%2,%3}, [%4];"
                 : "=r"(r0), "=r"(r1), "=r"(r2), "=r"(r3) : "r"(addr));
}
__device__ __forceinline__ void ldsm_x2_trans(
    uint32_t& r0, uint32_t& r1, uint32_t addr)
{
    asm volatile("ldmatrix.sync.aligned.m8n8.x2.trans.shared.b16 {%0,%1}, [%2];"
                 : "=r"(r0), "=r"(r1) : "r"(addr));
}
__device__ __forceinline__ void mma_f16(
    float* d, const uint32_t* a, uint32_t b0, uint32_t b1)
{
    asm volatile(
        "mma.sync.aligned.m16n8k16.row.col.f32.f16.f16.f32 "
        "{%0,%1,%2,%3}, {%4,%5,%6,%7}, {%8,%9}, {%0,%1,%2,%3};"
        : "+f"(d[0]), "+f"(d[1]), "+f"(d[2]), "+f"(d[3])
        : "r"(a[0]), "r"(a[1]), "r"(a[2]), "r"(a[3]), "r"(b0), "r"(b1));
}

// ============================================================================
// fp32 -> fp16 conversion (plain), 4 elems/thread.
// ============================================================================
__global__ __launch_bounds__(256) void f2h_kernel(
    const float* __restrict__ src, __half* __restrict__ dst)
{
    const size_t i = ((size_t)blockIdx.x * 256 + threadIdx.x) * 4;
    float4 v = *(const float4*)(src + i);
    __half2 h0 = __floats2half2_rn(v.x, v.y);
    __half2 h1 = __floats2half2_rn(v.z, v.w);
    uint2 o;
    o.x = *(uint32_t*)&h0; o.y = *(uint32_t*)&h1;
    *(uint2*)(dst + i) = o;
}

// ============================================================================
// w1/w3 -> interleaved fp16 w13: dst row 2t = w1[t], row 2t+1 = w3[t].
// ============================================================================
__global__ __launch_bounds__(256) void f2h_w13_kernel(
    const float* __restrict__ w1, const float* __restrict__ w3,
    __half* __restrict__ dst)
{
    const size_t i = ((size_t)blockIdx.x * 256 + threadIdx.x) * 4;
    const size_t t = i >> 10;           // / CC
    const size_t col = i & (CC - 1);
    float4 v = *(const float4*)(w1 + i);
    __half2 h0 = __floats2half2_rn(v.x, v.y);
    __half2 h1 = __floats2half2_rn(v.z, v.w);
    uint2 o;
    o.x = *(uint32_t*)&h0; o.y = *(uint32_t*)&h1;
    *(uint2*)(dst + (2 * t) * CC + col) = o;
    v = *(const float4*)(w3 + i);
    h0 = __floats2half2_rn(v.x, v.y);
    h1 = __floats2half2_rn(v.z, v.w);
    o.x = *(uint32_t*)&h0; o.y = *(uint32_t*)&h1;
    *(uint2*)(dst + (2 * t + 1) * CC + col) = o;
}

// ============================================================================
// LayerNorm: fp32 in, fp16 out. One row per block, 256 threads.
// ============================================================================
__global__ __launch_bounds__(256) void ln_kernel(
    const float* __restrict__ x, const float* __restrict__ g,
    const float* __restrict__ bta, __half* __restrict__ out)
{
    __shared__ float ssum[8], ssq[8];
    const int row = blockIdx.x;
    const int tid = threadIdx.x;

    const float4 v = *(const float4*)(x + (size_t)row * CC + tid * 4);
    float s = v.x + v.y + v.z + v.w;
    float q = v.x * v.x + v.y * v.y + v.z * v.z + v.w * v.w;

    #pragma unroll
    for (int off = 16; off; off >>= 1) {
        s += __shfl_xor_sync(0xffffffffu, s, off);
        q += __shfl_xor_sync(0xffffffffu, q, off);
    }
    if ((tid & 31) == 0) { ssum[tid >> 5] = s; ssq[tid >> 5] = q; }
    __syncthreads();

    float ts = 0.f, tq = 0.f;
    #pragma unroll
    for (int i = 0; i < 8; i++) { ts += ssum[i]; tq += ssq[i]; }

    const float mean = ts * (1.f / (float)CC);
    const float var  = tq * (1.f / (float)CC) - mean * mean;
    const float r    = rsqrtf(var + 1e-6f);

    const float4 gg = *(const float4*)(g + tid * 4);
    const float4 bb = *(const float4*)(bta + tid * 4);
    __half2 h0 = __floats2half2_rn((v.x - mean) * r * gg.x + bb.x,
                                   (v.y - mean) * r * gg.y + bb.y);
    __half2 h1 = __floats2half2_rn((v.z - mean) * r * gg.z + bb.z,
                                   (v.w - mean) * r * gg.w + bb.w);
    uint2 o;
    o.x = *(uint32_t*)&h0; o.y = *(uint32_t*)&h1;
    *(uint2*)(out + (size_t)row * CC + tid * 4) = o;
}

// ============================================================================
// fp16 tensor-core GEMM (NT), cp.async 4-stage pipeline + ldmatrix fragments.
// C[M,N] = A[M,K] @ B[N,K]^T (+bias) (+res). Outputs:
//   glu=0: fp32 C (if C) else fp16 Ch
//   glu=1: B is interleaved [w1;w3] -> Ch[row, col/2] = silu(a)*c  (N/2 wide)
// 128x128 CTA tile, 8 warps, K-chunk 32 halves. smem stride 20 uint32/row.
// ============================================================================
#define STRH 20
#define STG_U32 (128 * STRH)            // uint32 per matrix per stage
#define GEMM_SMEM (4 * 2 * STG_U32 * 4) // 81920 B

__global__ __launch_bounds__(256, 2) void gemm_h_kernel(
    const __half* __restrict__ A, const __half* __restrict__ B,
    const float* __restrict__ bias, const float* __restrict__ res,
    float* __restrict__ C, __half* __restrict__ Ch, int M, int N, int K,
    int glu)
{
    extern __shared__ uint32_t sm[];

    const int tid = threadIdx.x;
    const int wid = tid >> 5, lane = tid & 31;
    const int g = lane >> 2, qd = lane & 3;
    const int warpR = wid & 3, warpC = wid >> 2;
    const int m0 = blockIdx.y * 128, n0 = blockIdx.x * 128;

    const __half* Abase = A + (size_t)m0 * K;
    const __half* Bbase = B + (size_t)n0 * K;

    const int lr = tid >> 1;
    const int hsel = tid & 1;
    const size_t gsrc = (size_t)lr * K + hsel * 16;
    const uint32_t sbase = (uint32_t)__cvta_generic_to_shared(sm);
    const uint32_t dstoff = (uint32_t)(lr * STRH + hsel * 8) * 4;

    const uint32_t a_lane_off =
        (uint32_t)((warpR * 32 + (lane & 15)) * STRH + (lane >> 4) * 4) * 4;
    const uint32_t b_lane_off =
        (uint32_t)((warpC * 64 + (lane >> 4) * 8 + (lane & 7)) * STRH +
                   ((lane >> 3) & 1) * 4) * 4;

    float acc[2][8][4];
    #pragma unroll
    for (int mi = 0; mi < 2; mi++)
        #pragma unroll
        for (int nj = 0; nj < 8; nj++)
            #pragma unroll
            for (int e = 0; e < 4; e++) acc[mi][nj][e] = 0.f;

    const int nk = K >> 5;

    #pragma unroll
    for (int p = 0; p < 3; p++) {
        const uint32_t sa = sbase + (uint32_t)(2 * p) * (STG_U32 * 4) + dstoff;
        const uint32_t sb = sa + STG_U32 * 4;
        const int k0 = p * 32;
        cpa16(sa,      Abase + gsrc + k0);
        cpa16(sa + 16, Abase + gsrc + k0 + 8);
        cpa16(sb,      Bbase + gsrc + k0);
        cpa16(sb + 16, Bbase + gsrc + k0 + 8);
        CPA_COMMIT();
    }

    for (int kt = 0; kt < nk; kt++) {
        CPA_WAIT2();
        __syncthreads();

        const uint32_t sA = sbase + (uint32_t)(2 * (kt & 3)) * (STG_U32 * 4);
        const uint32_t sB = sA + STG_U32 * 4;
        #pragma unroll
        for (int ks = 0; ks < 2; ks++) {
            const uint32_t kso = (uint32_t)(ks * 8) * 4;
            uint32_t af[2][4];
            ldsm_x4(af[0][0], af[0][1], af[0][2], af[0][3],
                    sA + a_lane_off + kso);
            ldsm_x4(af[1][0], af[1][1], af[1][2], af[1][3],
                    sA + a_lane_off + kso + (uint32_t)(16 * STRH) * 4);
            #pragma unroll
            for (int np = 0; np < 4; np++) {
                uint32_t b0, b1, b2, b3;
                ldsm_x4(b0, b1, b2, b3,
                        sB + b_lane_off + kso + (uint32_t)(np * 16 * STRH) * 4);
                mma_f16(acc[0][np * 2],     af[0], b0, b1);
                mma_f16(acc[1][np * 2],     af[1], b0, b1);
                mma_f16(acc[0][np * 2 + 1], af[0], b2, b3);
                mma_f16(acc[1][np * 2 + 1], af[1], b2, b3);
            }
        }

        if (kt + 3 < nk) {
            const int p = (kt + 3) & 3;
            const uint32_t sa = sbase + (uint32_t)(2 * p) * (STG_U32 * 4) + dstoff;
            const uint32_t sb = sa + STG_U32 * 4;
            const int k0 = (kt + 3) * 32;
            cpa16(sa,      Abase + gsrc + k0);
            cpa16(sa + 16, Abase + gsrc + k0 + 8);
            cpa16(sb,      Bbase + gsrc + k0);
            cpa16(sb + 16, Bbase + gsrc + k0 + 8);
        }
        CPA_COMMIT();
    }

    // epilogue
    if (glu) {
        const int No = N >> 1;   // gated output width
        #pragma unroll
        for (int mi = 0; mi < 2; mi++) {
            const int rowa = m0 + warpR * 32 + mi * 16 + g;
            #pragma unroll
            for (int nj = 0; nj < 8; nj++) {
                // FIX (R14 bug): include warpC*64 in the output column
                const int colo = (n0 + warpC * 64 + nj * 8 + 2 * qd) >> 1;
                const float a0 = acc[mi][nj][0], c0 = acc[mi][nj][1];
                const float a1 = acc[mi][nj][2], c1 = acc[mi][nj][3];
                const float g0 = a0 * c0 / (1.f + __expf(-a0));
                const float g1 = a1 * c1 / (1.f + __expf(-a1));
                Ch[(size_t)rowa * No + colo] = __float2half_rn(g0);
                Ch[(size_t)(rowa + 8) * No + colo] = __float2half_rn(g1);
            }
        }
        return;
    }
    #pragma unroll
    for (int mi = 0; mi < 2; mi++) {
        const int rowa = m0 + warpR * 32 + mi * 16 + g;
        #pragma unroll
        for (int nj = 0; nj < 8; nj++) {
            const int col = n0 + warpC * 64 + nj * 8 + 2 * qd;
            float2 v0 = make_float2(acc[mi][nj][0], acc[mi][nj][1]);
            float2 v1 = make_float2(acc[mi][nj][2], acc[mi][nj][3]);
            if (bias) {
                const float bx = bias[col], by = bias[col + 1];
                v0.x += bx; v0.y += by;
                v1.x += bx; v1.y += by;
            }
            if (res) {
                float2 r0 = *(const float2*)(res + (size_t)rowa * N + col);
                float2 r1 = *(const float2*)(res + (size_t)(rowa + 8) * N + col);
                v0.x += r0.x; v0.y += r0.y;
                v1.x += r1.x; v1.y += r1.y;
            }
            if (C) {
                *(float2*)(C + (size_t)rowa * N + col) = v0;
                *(float2*)(C + (size_t)(rowa + 8) * N + col) = v1;
            } else {
                __half2 h0 = __floats2half2_rn(v0.x, v0.y);
                __half2 h1 = __floats2half2_rn(v1.x, v1.y);
                *(__half2*)(Ch + (size_t)rowa * N + col) = h0;
                *(__half2*)(Ch + (size_t)(rowa + 8) * N + col) = h1;
            }
        }
    }
}

// ============================================================================
// fp16 tensor-core flash attention (causal), fp32 softmax.
// 256 threads (8 warps). Br=128, Bc=64, D=64. Warp w owns Q rows [w*16,w*16+16).
// Q/K/V fp16 in smem (stride 36 u32 = 72 halves, conflict-free).
// S=QK^T: m16n8k16, direct LDS.32 frags. P: S c-frag packs straight into the
// PV a-frag (FA2 trick). V b-frags via ldmatrix.x2.trans. K/V via cp.async.
// ============================================================================
#define HST 36
#define ATT_SMEM ((128 * HST + 4 * 64 * HST) * 4)   // Q + 2xK + 2xV = 55296 B

__global__ __launch_bounds__(256) void attn_kernel(
    const __half* __restrict__ qkv, __half* __restrict__ out)
{
    extern __shared__ uint32_t sh[];
    uint32_t* Qs = sh;                         // 128*HST
    const uint32_t KOFF0 = 128 * HST;
    const uint32_t KOFF1 = KOFF0 + 64 * HST;
    const uint32_t VOFF0 = KOFF1 + 64 * HST;
    const uint32_t VOFF1 = VOFF0 + 64 * HST;
    const uint32_t shb = (uint32_t)__cvta_generic_to_shared(sh);

    const int tid = threadIdx.x;
    const int wid = tid >> 5, lane = tid & 31;
    const int g = lane >> 2, qd = lane & 3;
    const int qb = blockIdx.x;
    const int bh = blockIdx.y;
    const int b = bh >> 4, h = bh & 15;
    const int i0 = qb << 7;
    const size_t base = (size_t)b * NN * (3 * CC) + h * DD;

    // ---- load Q (scaled by 1/8), fp16 ----
    const __half2 sc8 = __floats2half2_rn(0.125f, 0.125f);
    #pragma unroll
    for (int l = 0; l < 4; l++) {
        const int idx = tid + l * 256;          // 1024 uint4 chunks
        const int r = idx >> 3, q = idx & 7;
        uint4 raw = *(const uint4*)(qkv + base + (size_t)(i0 + r) * (3 * CC) + q * 8);
        __half2* hp = (__half2*)&raw;
        hp[0] = __hmul2(hp[0], sc8); hp[1] = __hmul2(hp[1], sc8);
        hp[2] = __hmul2(hp[2], sc8); hp[3] = __hmul2(hp[3], sc8);
        *(uint4*)&Qs[r * HST + q * 4] = raw;
    }

    // K/V loader geometry: 512 uint4 per 64x64 tile; 2 per thread each
    const int lr0 = tid >> 3, lq0 = tid & 7;
    const int lr1 = (tid + 256) >> 3, lq1 = (tid + 256) & 7;

    // prologue: K/V tile 0 -> stage 0
    {
        cpa16(shb + (KOFF0 + lr0 * HST + lq0 * 4) * 4,
              qkv + base + CC + (size_t)lr0 * (3 * CC) + lq0 * 8);
        cpa16(shb + (KOFF0 + lr1 * HST + lq1 * 4) * 4,
              qkv + base + CC + (size_t)lr1 * (3 * CC) + lq1 * 8);
        cpa16(shb + (VOFF0 + lr0 * HST + lq0 * 4) * 4,
              qkv + base + 2 * CC + (size_t)lr0 * (3 * CC) + lq0 * 8);
        cpa16(shb + (VOFF0 + lr1 * HST + lq1 * 4) * 4,
              qkv + base + 2 * CC + (size_t)lr1 * (3 * CC) + lq1 * 8);
        CPA_COMMIT();
    }

    float o[8][4];
    #pragma unroll
    for (int nj = 0; nj < 8; nj++)
        #pragma unroll
        for (int ee = 0; ee < 4; ee++) o[nj][ee] = 0.f;
    float m0 = -1e30f, m1 = -1e30f, l0 = 0.f, l1 = 0.f;

    const int rbq = (wid * 16 + g) * HST;
    const int row0 = i0 + wid * 16 + g;
    const int kbmax = 2 * qb + 1;

    for (int kb = 0; kb <= kbmax; kb++) {
        __syncthreads();   // readers of the stage we're about to overwrite done
        if (kb < kbmax) {
            const int nk0 = (kb + 1) << 6;
            const uint32_t KO = (kb & 1) ? KOFF0 : KOFF1;  // next stage
            const uint32_t VO = (kb & 1) ? VOFF0 : VOFF1;
            cpa16(shb + (KO + lr0 * HST + lq0 * 4) * 4,
                  qkv + base + CC + (size_t)(nk0 + lr0) * (3 * CC) + lq0 * 8);
            cpa16(shb + (KO + lr1 * HST + lq1 * 4) * 4,
                  qkv + base + CC + (size_t)(nk0 + lr1) * (3 * CC) + lq1 * 8);
            cpa16(shb + (VO + lr0 * HST + lq0 * 4) * 4,
                  qkv + base + 2 * CC + (size_t)(nk0 + lr0) * (3 * CC) + lq0 * 8);
            cpa16(shb + (VO + lr1 * HST + lq1 * 4) * 4,
                  qkv + base + 2 * CC + (size_t)(nk0 + lr1) * (3 * CC) + lq1 * 8);
        }
        CPA_COMMIT();
        CPA_WAIT1();       // current tile's group complete
        __syncthreads();

        const uint32_t* Ksc = sh + ((kb & 1) ? KOFF1 : KOFF0);
        const uint32_t VsO = (kb & 1) ? VOFF1 : VOFF0;
        const int k0r = kb << 6;

        // ---- S = Q K^T (fp16 MMA) ----
        float s[8][4];
        #pragma unroll
        for (int nj = 0; nj < 8; nj++)
            #pragma unroll
            for (int ee = 0; ee < 4; ee++) s[nj][ee] = 0.f;

        #pragma unroll
        for (int kc = 0; kc < 4; kc++) {
            const int ko = kc * 8 + qd;
            uint32_t af[4];
            af[0] = Qs[rbq + ko];
            af[1] = Qs[rbq + 8 * HST + ko];
            af[2] = Qs[rbq + ko + 4];
            af[3] = Qs[rbq + 8 * HST + ko + 4];
            #pragma unroll
            for (int nj = 0; nj < 8; nj++) {
                const int kr = (nj * 8 + g) * HST;
                mma_f16(s[nj], af, Ksc[kr + ko], Ksc[kr + ko + 4]);
            }
        }

        // causal mask
        if (kb >= 2 * qb) {
            #pragma unroll
            for (int nj = 0; nj < 8; nj++) {
                const int col = k0r + nj * 8 + 2 * qd;
                if (col > row0)     s[nj][0] = -1e30f;
                if (col + 1 > row0) s[nj][1] = -1e30f;
                if (col > row0 + 8)     s[nj][2] = -1e30f;
                if (col + 1 > row0 + 8) s[nj][3] = -1e30f;
            }
        }

        // ---- online softmax ----
        float mx0 = -1e30f, mx1 = -1e30f;
        #pragma unroll
        for (int nj = 0; nj < 8; nj++) {
            mx0 = fmaxf(mx0, fmaxf(s[nj][0], s[nj][1]));
            mx1 = fmaxf(mx1, fmaxf(s[nj][2], s[nj][3]));
        }
        mx0 = fmaxf(mx0, __shfl_xor_sync(0xffffffffu, mx0, 1));
        mx0 = fmaxf(mx0, __shfl_xor_sync(0xffffffffu, mx0, 2));
        mx1 = fmaxf(mx1, __shfl_xor_sync(0xffffffffu, mx1, 1));
        mx1 = fmaxf(mx1, __shfl_xor_sync(0xffffffffu, mx1, 2));

        const float mn0 = fmaxf(m0, mx0), mn1 = fmaxf(m1, mx1);
        const float al0 = __expf(m0 - mn0), al1 = __expf(m1 - mn1);
        m0 = mn0; m1 = mn1;

        float rs0 = 0.f, rs1 = 0.f;
        #pragma unroll
        for (int nj = 0; nj < 8; nj++) {
            s[nj][0] = __expf(s[nj][0] - mn0); rs0 += s[nj][0];
            s[nj][1] = __expf(s[nj][1] - mn0); rs0 += s[nj][1];
            s[nj][2] = __expf(s[nj][2] - mn1); rs1 += s[nj][2];
            s[nj][3] = __expf(s[nj][3] - mn1); rs1 += s[nj][3];
        }
        rs0 += __shfl_xor_sync(0xffffffffu, rs0, 1);
        rs0 += __shfl_xor_sync(0xffffffffu, rs0, 2);
        rs1 += __shfl_xor_sync(0xffffffffu, rs1, 1);
        rs1 += __shfl_xor_sync(0xffffffffu, rs1, 2);
        l0 = l0 * al0 + rs0;
        l1 = l1 * al1 + rs1;

        #pragma unroll
        for (int nj = 0; nj < 8; nj++) {
            o[nj][0] *= al0; o[nj][1] *= al0;
            o[nj][2] *= al1; o[nj][3] *= al1;
        }

        // ---- O += P @ V (fp16 MMA; P a-frags packed from S c-frags) ----
        #pragma unroll
        for (int kc = 0; kc < 4; kc++) {
            uint32_t af[4];
            af[0] = packh2(s[2 * kc][0],     s[2 * kc][1]);
            af[1] = packh2(s[2 * kc][2],     s[2 * kc][3]);
            af[2] = packh2(s[2 * kc + 1][0], s[2 * kc + 1][1]);
            af[3] = packh2(s[2 * kc + 1][2], s[2 * kc + 1][3]);
            const uint32_t vrow = VsO + (uint32_t)(kc * 16 + (lane & 15)) * HST;
            #pragma unroll
            for (int nj = 0; nj < 8; nj++) {
                uint32_t b0, b1;
                ldsm_x2_trans(b0, b1, shb + (vrow + nj * 4) * 4);
                mma_f16(o[nj], af, b0, b1);
            }
        }
    }

    // epilogue
    const float inv0 = 1.f / l0, inv1 = 1.f / l1;
    const int orow = b * NN + row0;
    #pragma unroll
    for (int nj = 0; nj < 8; nj++) {
        const int col = h * DD + nj * 8 + 2 * qd;
        __half2 h0 = __floats2half2_rn(o[nj][0] * inv0, o[nj][1] * inv0);
        __half2 h1 = __floats2half2_rn(o[nj][2] * inv1, o[nj][3] * inv1);
        *(__half2*)(out + (size_t)orow * CC + col) = h0;
        *(__half2*)(out + (size_t)(orow + 8) * CC + col) = h1;
    }
}

// ============================================================================
// Launch
// ============================================================================
extern "C" void kernel_launch(void* const* d_in, const int* in_sizes, int n_in,
                              void* d_out, int out_size)
{
    const float* x      = (const float*)d_in[0];
    // d_in[1] = mask (causal tril, hardcoded in attn kernel)
    const float* qkv_w  = (const float*)d_in[2];
    const float* qkv_b  = (const float*)d_in[3];
    const float* proj_w = (const float*)d_in[4];
    const float* proj_b = (const float*)d_in[5];
    const float* ln1_g  = (const float*)d_in[6];
    const float* ln1_b  = (const float*)d_in[7];
    const float* ln2_g  = (const float*)d_in[8];
    const float* ln2_b  = (const float*)d_in[9];
    const float* w1     = (const float*)d_in[10];
    const float* w2     = (const float*)d_in[11];
    const float* w3     = (const float*)d_in[12];
    float* out = (float*)d_out;

    __half *qkvw_h, *projw_h, *w13_h, *w2_h;
    __half *hh, *qkvh, *attnh, *b1h;
    float* x1;
    cudaGetSymbolAddress((void**)&qkvw_h, g_qkvw_h);
    cudaGetSymbolAddress((void**)&projw_h, g_projw_h);
    cudaGetSymbolAddress((void**)&w13_h, g_w13_h);
    cudaGetSymbolAddress((void**)&w2_h, g_w2_h);
    cudaGetSymbolAddress((void**)&hh,   g_h_h);
    cudaGetSymbolAddress((void**)&qkvh, g_qkv_h);
    cudaGetSymbolAddress((void**)&attnh, g_attn_h);
    cudaGetSymbolAddress((void**)&x1,   g_x1);
    cudaGetSymbolAddress((void**)&b1h,  g_b1_h);

    cudaFuncSetAttribute(attn_kernel,
                         cudaFuncAttributeMaxDynamicSharedMemorySize, ATT_SMEM);
    cudaFuncSetAttribute(gemm_h_kernel,
                         cudaFuncAttributeMaxDynamicSharedMemorySize, GEMM_SMEM);

    // 0. weights -> fp16 (w1/w3 interleaved)
    f2h_kernel<<<(3 * CC * CC) / 1024, 256>>>(qkv_w, qkvw_h);
    f2h_kernel<<<(CC * CC) / 1024, 256>>>(proj_w, projw_h);
    f2h_w13_kernel<<<(FFD * CC) / 1024, 256>>>(w1, w3, w13_h);
    f2h_kernel<<<(CC * FFD) / 1024, 256>>>(w2, w2_h);

    // 1. LN1 (fp16 out)
    ln_kernel<<<MROWS, 256>>>(x, ln1_g, ln1_b, hh);
    // 2. qkv = h @ qkv_w^T + qkv_b -> fp16   [8192, 3072]
    gemm_h_kernel<<<dim3(3 * CC / 128, MROWS / 128), 256, GEMM_SMEM>>>(
        hh, qkvw_h, qkv_b, nullptr, nullptr, qkvh, MROWS, 3 * CC, CC, 0);
    // 3. causal flash attention -> fp16
    attn_kernel<<<dim3(NN / 128, BB * HH), 256, ATT_SMEM>>>(qkvh, attnh);
    // 4. x1 = x + attn @ proj_w^T + proj_b -> fp32
    gemm_h_kernel<<<dim3(CC / 128, MROWS / 128), 256, GEMM_SMEM>>>(
        attnh, projw_h, proj_b, x, x1, nullptr, MROWS, CC, CC, 0);
    // 5. LN2 (fp16 out)
    ln_kernel<<<MROWS, 256>>>(x1, ln2_g, ln2_b, hh);
    // 6. b1 = silu(h@w1^T) * (h@w3^T) fused  [8192, 4096] (N=8192 interleaved)
    gemm_h_kernel<<<dim3(2 * FFD / 128, MROWS / 128), 256, GEMM_SMEM>>>(
        hh, w13_h, nullptr, nullptr, nullptr, b1h, MROWS, 2 * FFD, CC, 1);
    // 7. out = x1 + b1 @ w2^T -> fp32        [8192, 1024]
    gemm_h_kernel<<<dim3(CC / 128, MROWS / 128), 256, GEMM_SMEM>>>(
        b1h, w2_h, nullptr, x1, out, nullptr, MROWS, CC, FFD, 0);
}

// round 17
// speedup vs baseline: 1.3894x; 1.3894x over previous
#include <cuda_runtime.h>
#include <cuda_fp16.h>
#include <math.h>
#include <stdint.h>

// Problem constants
#define BB 4
#define NN 2048
#define CC 1024
#define HH 16
#define DD 64
#define FFD 4096
#define MROWS (BB * NN)   // 8192

// -------------------- scratch (allocation-free: __device__ globals) ---------
__device__ __half g_qkvw_h[3 * CC * CC];
__device__ __half g_projw_h[CC * CC];
__device__ __half g_w13_h[2 * FFD * CC];   // interleaved: row 2t=w1[t], 2t+1=w3[t]
__device__ __half g_w2_h[CC * FFD];

__device__ __half g_h_h[MROWS * CC];       // LN output (fp16)
__device__ __half g_qkv_h[MROWS * 3 * CC]; // qkv projection (fp16)
__device__ __half g_attn_h[MROWS * CC];    // attention output (fp16)
__device__ float  g_x1[MROWS * CC];        // x + attn_proj (fp32 residual)
__device__ __half g_b1_h[MROWS * FFD];     // silu(h@w1^T)*(h@w3^T) (fp16)

// ======================= portable PTX helpers (sm_80+) ======================
__device__ __forceinline__ uint32_t f32_to_tf32(float x) {
    uint32_t u;
    asm("cvt.rna.tf32.f32 %0, %1;" : "=r"(u) : "f"(x));
    return u;
}
__device__ __forceinline__ void cpa16(uint32_t dst, const void* src) {
    asm volatile("cp.async.ca.shared.global [%0], [%1], 16;"
                 :: "r"(dst), "l"(src));
}
#define CPA_COMMIT() asm volatile("cp.async.commit_group;" ::: "memory")
#define CPA_WAIT2()  asm volatile("cp.async.wait_group 2;" ::: "memory")

__device__ __forceinline__ void ldsm_x4(
    uint32_t& r0, uint32_t& r1, uint32_t& r2, uint32_t& r3, uint32_t addr)
{
    asm volatile("ldmatrix.sync.aligned.m8n8.x4.shared.b16 {%0,%1,%2,%3}, [%4];"
                 : "=r"(r0), "=r"(r1), "=r"(r2), "=r"(r3) : "r"(addr));
}
__device__ __forceinline__ void mma_tf32(
    float* d, const uint32_t* a, uint32_t b0, uint32_t b1)
{
    asm volatile(
        "mma.sync.aligned.m16n8k8.row.col.f32.tf32.tf32.f32 "
        "{%0,%1,%2,%3}, {%4,%5,%6,%7}, {%8,%9}, {%0,%1,%2,%3};"
        : "+f"(d[0]), "+f"(d[1]), "+f"(d[2]), "+f"(d[3])
        : "r"(a[0]), "r"(a[1]), "r"(a[2]), "r"(a[3]), "r"(b0), "r"(b1));
}
__device__ __forceinline__ void mma_f16(
    float* d, const uint32_t* a, uint32_t b0, uint32_t b1)
{
    asm volatile(
        "mma.sync.aligned.m16n8k16.row.col.f32.f16.f16.f32 "
        "{%0,%1,%2,%3}, {%4,%5,%6,%7}, {%8,%9}, {%0,%1,%2,%3};"
        : "+f"(d[0]), "+f"(d[1]), "+f"(d[2]), "+f"(d[3])
        : "r"(a[0]), "r"(a[1]), "r"(a[2]), "r"(a[3]), "r"(b0), "r"(b1));
}

// ============================================================================
// fp32 -> fp16 conversion (plain), 4 elems/thread.
// ============================================================================
__global__ __launch_bounds__(256) void f2h_kernel(
    const float* __restrict__ src, __half* __restrict__ dst)
{
    const size_t i = ((size_t)blockIdx.x * 256 + threadIdx.x) * 4;
    float4 v = *(const float4*)(src + i);
    __half2 h0 = __floats2half2_rn(v.x, v.y);
    __half2 h1 = __floats2half2_rn(v.z, v.w);
    uint2 o;
    o.x = *(uint32_t*)&h0; o.y = *(uint32_t*)&h1;
    *(uint2*)(dst + i) = o;
}

// ============================================================================
// w1/w3 -> interleaved fp16 w13: dst row 2t = w1[t], row 2t+1 = w3[t].
// ============================================================================
__global__ __launch_bounds__(256) void f2h_w13_kernel(
    const float* __restrict__ w1, const float* __restrict__ w3,
    __half* __restrict__ dst)
{
    const size_t i = ((size_t)blockIdx.x * 256 + threadIdx.x) * 4;
    const size_t t = i >> 10;           // / CC
    const size_t col = i & (CC - 1);
    float4 v = *(const float4*)(w1 + i);
    __half2 h0 = __floats2half2_rn(v.x, v.y);
    __half2 h1 = __floats2half2_rn(v.z, v.w);
    uint2 o;
    o.x = *(uint32_t*)&h0; o.y = *(uint32_t*)&h1;
    *(uint2*)(dst + (2 * t) * CC + col) = o;
    v = *(const float4*)(w3 + i);
    h0 = __floats2half2_rn(v.x, v.y);
    h1 = __floats2half2_rn(v.z, v.w);
    o.x = *(uint32_t*)&h0; o.y = *(uint32_t*)&h1;
    *(uint2*)(dst + (2 * t + 1) * CC + col) = o;
}

// ============================================================================
// LayerNorm: fp32 in, fp16 out. One row per block, 256 threads.
// ============================================================================
__global__ __launch_bounds__(256) void ln_kernel(
    const float* __restrict__ x, const float* __restrict__ g,
    const float* __restrict__ bta, __half* __restrict__ out)
{
    __shared__ float ssum[8], ssq[8];
    const int row = blockIdx.x;
    const int tid = threadIdx.x;

    const float4 v = *(const float4*)(x + (size_t)row * CC + tid * 4);
    float s = v.x + v.y + v.z + v.w;
    float q = v.x * v.x + v.y * v.y + v.z * v.z + v.w * v.w;

    #pragma unroll
    for (int off = 16; off; off >>= 1) {
        s += __shfl_xor_sync(0xffffffffu, s, off);
        q += __shfl_xor_sync(0xffffffffu, q, off);
    }
    if ((tid & 31) == 0) { ssum[tid >> 5] = s; ssq[tid >> 5] = q; }
    __syncthreads();

    float ts = 0.f, tq = 0.f;
    #pragma unroll
    for (int i = 0; i < 8; i++) { ts += ssum[i]; tq += ssq[i]; }

    const float mean = ts * (1.f / (float)CC);
    const float var  = tq * (1.f / (float)CC) - mean * mean;
    const float r    = rsqrtf(var + 1e-6f);

    const float4 gg = *(const float4*)(g + tid * 4);
    const float4 bb = *(const float4*)(bta + tid * 4);
    __half2 h0 = __floats2half2_rn((v.x - mean) * r * gg.x + bb.x,
                                   (v.y - mean) * r * gg.y + bb.y);
    __half2 h1 = __floats2half2_rn((v.z - mean) * r * gg.z + bb.z,
                                   (v.w - mean) * r * gg.w + bb.w);
    uint2 o;
    o.x = *(uint32_t*)&h0; o.y = *(uint32_t*)&h1;
    *(uint2*)(out + (size_t)row * CC + tid * 4) = o;
}

// ============================================================================
// fp16 tensor-core GEMM (NT), cp.async 4-stage pipeline + ldmatrix fragments.
// C[M,N] = A[M,K] @ B[N,K]^T (+bias) (+res). Outputs:
//   glu=0: fp32 C (if C) else fp16 Ch
//   glu=1: B is interleaved [w1;w3] -> Ch[row, col/2] = silu(a)*c  (N/2 wide)
// 128x128 CTA tile, 8 warps, K-chunk 32 halves. smem stride 20 uint32/row.
// ============================================================================
#define STRH 20
#define STG_U32 (128 * STRH)            // uint32 per matrix per stage
#define GEMM_SMEM (4 * 2 * STG_U32 * 4) // 81920 B

__global__ __launch_bounds__(256, 2) void gemm_h_kernel(
    const __half* __restrict__ A, const __half* __restrict__ B,
    const float* __restrict__ bias, const float* __restrict__ res,
    float* __restrict__ C, __half* __restrict__ Ch, int M, int N, int K,
    int glu)
{
    extern __shared__ uint32_t sm[];

    const int tid = threadIdx.x;
    const int wid = tid >> 5, lane = tid & 31;
    const int g = lane >> 2, qd = lane & 3;
    const int warpR = wid & 3, warpC = wid >> 2;
    const int m0 = blockIdx.y * 128, n0 = blockIdx.x * 128;

    const __half* Abase = A + (size_t)m0 * K;
    const __half* Bbase = B + (size_t)n0 * K;

    const int lr = tid >> 1;
    const int hsel = tid & 1;
    const size_t gsrc = (size_t)lr * K + hsel * 16;
    const uint32_t sbase = (uint32_t)__cvta_generic_to_shared(sm);
    const uint32_t dstoff = (uint32_t)(lr * STRH + hsel * 8) * 4;

    const uint32_t a_lane_off =
        (uint32_t)((warpR * 32 + (lane & 15)) * STRH + (lane >> 4) * 4) * 4;
    const uint32_t b_lane_off =
        (uint32_t)((warpC * 64 + (lane >> 4) * 8 + (lane & 7)) * STRH +
                   ((lane >> 3) & 1) * 4) * 4;

    float acc[2][8][4];
    #pragma unroll
    for (int mi = 0; mi < 2; mi++)
        #pragma unroll
        for (int nj = 0; nj < 8; nj++)
            #pragma unroll
            for (int e = 0; e < 4; e++) acc[mi][nj][e] = 0.f;

    const int nk = K >> 5;

    #pragma unroll
    for (int p = 0; p < 3; p++) {
        const uint32_t sa = sbase + (uint32_t)(2 * p) * (STG_U32 * 4) + dstoff;
        const uint32_t sb = sa + STG_U32 * 4;
        const int k0 = p * 32;
        cpa16(sa,      Abase + gsrc + k0);
        cpa16(sa + 16, Abase + gsrc + k0 + 8);
        cpa16(sb,      Bbase + gsrc + k0);
        cpa16(sb + 16, Bbase + gsrc + k0 + 8);
        CPA_COMMIT();
    }

    for (int kt = 0; kt < nk; kt++) {
        CPA_WAIT2();
        __syncthreads();

        const uint32_t sA = sbase + (uint32_t)(2 * (kt & 3)) * (STG_U32 * 4);
        const uint32_t sB = sA + STG_U32 * 4;
        #pragma unroll
        for (int ks = 0; ks < 2; ks++) {
            const uint32_t kso = (uint32_t)(ks * 8) * 4;
            uint32_t af[2][4];
            ldsm_x4(af[0][0], af[0][1], af[0][2], af[0][3],
                    sA + a_lane_off + kso);
            ldsm_x4(af[1][0], af[1][1], af[1][2], af[1][3],
                    sA + a_lane_off + kso + (uint32_t)(16 * STRH) * 4);
            #pragma unroll
            for (int np = 0; np < 4; np++) {
                uint32_t b0, b1, b2, b3;
                ldsm_x4(b0, b1, b2, b3,
                        sB + b_lane_off + kso + (uint32_t)(np * 16 * STRH) * 4);
                mma_f16(acc[0][np * 2],     af[0], b0, b1);
                mma_f16(acc[1][np * 2],     af[1], b0, b1);
                mma_f16(acc[0][np * 2 + 1], af[0], b2, b3);
                mma_f16(acc[1][np * 2 + 1], af[1], b2, b3);
            }
        }

        if (kt + 3 < nk) {
            const int p = (kt + 3) & 3;
            const uint32_t sa = sbase + (uint32_t)(2 * p) * (STG_U32 * 4) + dstoff;
            const uint32_t sb = sa + STG_U32 * 4;
            const int k0 = (kt + 3) * 32;
            cpa16(sa,      Abase + gsrc + k0);
            cpa16(sa + 16, Abase + gsrc + k0 + 8);
            cpa16(sb,      Bbase + gsrc + k0);
            cpa16(sb + 16, Bbase + gsrc + k0 + 8);
        }
        CPA_COMMIT();
    }

    // epilogue
    if (glu) {
        const int No = N >> 1;   // gated output width
        #pragma unroll
        for (int mi = 0; mi < 2; mi++) {
            const int rowa = m0 + warpR * 32 + mi * 16 + g;
            #pragma unroll
            for (int nj = 0; nj < 8; nj++) {
                const int colo = (n0 + warpC * 64 + nj * 8 + 2 * qd) >> 1;
                const float a0 = acc[mi][nj][0], c0 = acc[mi][nj][1];
                const float a1 = acc[mi][nj][2], c1 = acc[mi][nj][3];
                const float g0 = a0 * c0 / (1.f + __expf(-a0));
                const float g1 = a1 * c1 / (1.f + __expf(-a1));
                Ch[(size_t)rowa * No + colo] = __float2half_rn(g0);
                Ch[(size_t)(rowa + 8) * No + colo] = __float2half_rn(g1);
            }
        }
        return;
    }
    #pragma unroll
    for (int mi = 0; mi < 2; mi++) {
        const int rowa = m0 + warpR * 32 + mi * 16 + g;
        #pragma unroll
        for (int nj = 0; nj < 8; nj++) {
            const int col = n0 + warpC * 64 + nj * 8 + 2 * qd;
            float2 v0 = make_float2(acc[mi][nj][0], acc[mi][nj][1]);
            float2 v1 = make_float2(acc[mi][nj][2], acc[mi][nj][3]);
            if (bias) {
                const float bx = bias[col], by = bias[col + 1];
                v0.x += bx; v0.y += by;
                v1.x += bx; v1.y += by;
            }
            if (res) {
                float2 r0 = *(const float2*)(res + (size_t)rowa * N + col);
                float2 r1 = *(const float2*)(res + (size_t)(rowa + 8) * N + col);
                v0.x += r0.x; v0.y += r0.y;
                v1.x += r1.x; v1.y += r1.y;
            }
            if (C) {
                *(float2*)(C + (size_t)rowa * N + col) = v0;
                *(float2*)(C + (size_t)(rowa + 8) * N + col) = v1;
            } else {
                __half2 h0 = __floats2half2_rn(v0.x, v0.y);
                __half2 h1 = __floats2half2_rn(v1.x, v1.y);
                *(__half2*)(Ch + (size_t)rowa * N + col) = h0;
                *(__half2*)(Ch + (size_t)(rowa + 8) * N + col) = h1;
            }
        }
    }
}

// ============================================================================
// Tensor-core flash attention (causal), tf32 MMA + fp32 softmax.  [R13 exact]
// fp16 qkv input, fp16 output. 256 threads, Br=128, Bc=64, D=64.
// ============================================================================
#define AST 68
#define VST 72
#define ATT_SMEM ((128 * AST + 2 * 64 * AST + 2 * 64 * VST) * 4)

__global__ __launch_bounds__(256) void attn_kernel(
    const __half* __restrict__ qkv, __half* __restrict__ out)
{
    extern __shared__ uint32_t sh[];
    uint32_t* Qs = sh;
    uint32_t* Ks0 = sh + 128 * AST;
    uint32_t* Ks1 = Ks0 + 64 * AST;
    uint32_t* Vs0 = Ks1 + 64 * AST;
    uint32_t* Vs1 = Vs0 + 64 * VST;

    const int tid = threadIdx.x;
    const int wid = tid >> 5, lane = tid & 31;
    const int g = lane >> 2, qd = lane & 3;
    const int qb = blockIdx.x;
    const int bh = blockIdx.y;
    const int b = bh >> 4, h = bh & 15;
    const int i0 = qb << 7;
    const size_t base = (size_t)b * NN * (3 * CC) + h * DD;

    const int e = qd & 1;
    const int srcA = (lane & ~3) | (qd >> 1);
    const int srcB = srcA + 2;

    #pragma unroll
    for (int l = 0; l < 8; l++) {
        const int idx = tid + l * 256;
        const int r = idx >> 4, c = (idx & 15) << 2;
        uint2 raw = *(const uint2*)(qkv + base + (size_t)(i0 + r) * (3 * CC) + c);
        float2 f0 = __half22float2(*(__half2*)&raw.x);
        float2 f1 = __half22float2(*(__half2*)&raw.y);
        uint4 t;
        t.x = f32_to_tf32(f0.x * 0.125f); t.y = f32_to_tf32(f0.y * 0.125f);
        t.z = f32_to_tf32(f1.x * 0.125f); t.w = f32_to_tf32(f1.y * 0.125f);
        *(uint4*)&Qs[r * AST + c] = t;
    }

    const int lr[4] = { tid >> 4, (tid + 256) >> 4, (tid + 512) >> 4, (tid + 768) >> 4 };
    const int lc = (tid & 15) << 2;

    #pragma unroll
    for (int l = 0; l < 4; l++) {
        const int c = lr[l];
        uint2 kraw = *(const uint2*)(qkv + base + CC + (size_t)c * (3 * CC) + lc);
        float2 f0 = __half22float2(*(__half2*)&kraw.x);
        float2 f1 = __half22float2(*(__half2*)&kraw.y);
        uint4 t;
        t.x = f32_to_tf32(f0.x); t.y = f32_to_tf32(f0.y);
        t.z = f32_to_tf32(f1.x); t.w = f32_to_tf32(f1.y);
        *(uint4*)&Ks0[c * AST + lc] = t;
        uint2 vraw = *(const uint2*)(qkv + base + 2 * CC + (size_t)c * (3 * CC) + lc);
        f0 = __half22float2(*(__half2*)&vraw.x);
        f1 = __half22float2(*(__half2*)&vraw.y);
        t.x = f32_to_tf32(f0.x); t.y = f32_to_tf32(f0.y);
        t.z = f32_to_tf32(f1.x); t.w = f32_to_tf32(f1.y);
        *(uint4*)&Vs0[c * VST + lc] = t;
    }
    __syncthreads();

    float o[8][4];
    #pragma unroll
    for (int nj = 0; nj < 8; nj++)
        #pragma unroll
        for (int ee = 0; ee < 4; ee++) o[nj][ee] = 0.f;
    float m0 = -1e30f, m1 = -1e30f, l0 = 0.f, l1 = 0.f;

    const int rb = (wid * 16 + g) * AST;
    const int row0 = i0 + wid * 16 + g;
    const int kbmax = 2 * qb + 1;

    for (int kb = 0; kb <= kbmax; kb++) {
        const uint32_t* Ksc = (kb & 1) ? Ks1 : Ks0;
        const uint32_t* Vsc = (kb & 1) ? Vs1 : Vs0;
        uint32_t* Ksn = (kb & 1) ? Ks0 : Ks1;
        uint32_t* Vsn = (kb & 1) ? Vs0 : Vs1;
        const int k0r = kb << 6;
        const bool pref = (kb < kbmax);

        uint2 kreg[4], vreg[4];
        if (pref) {
            const int nk0 = k0r + 64;
            #pragma unroll
            for (int l = 0; l < 4; l++) {
                kreg[l] = *(const uint2*)(qkv + base + CC + (size_t)(nk0 + lr[l]) * (3 * CC) + lc);
                vreg[l] = *(const uint2*)(qkv + base + 2 * CC + (size_t)(nk0 + lr[l]) * (3 * CC) + lc);
            }
        }

        float s[8][4];
        #pragma unroll
        for (int nj = 0; nj < 8; nj++)
            #pragma unroll
            for (int ee = 0; ee < 4; ee++) s[nj][ee] = 0.f;

        #pragma unroll
        for (int ks = 0; ks < 8; ks++) {
            const int kc0 = ks * 8 + qd;
            uint32_t af[4];
            af[0] = Qs[rb + kc0];
            af[1] = Qs[rb + 8 * AST + kc0];
            af[2] = Qs[rb + kc0 + 4];
            af[3] = Qs[rb + 8 * AST + kc0 + 4];
            #pragma unroll
            for (int nj = 0; nj < 8; nj++) {
                const int nb = (nj * 8 + g) * AST;
                mma_tf32(s[nj], af, Ksc[nb + kc0], Ksc[nb + kc0 + 4]);
            }
        }

        if (kb >= 2 * qb) {
            #pragma unroll
            for (int nj = 0; nj < 8; nj++) {
                const int col = k0r + nj * 8 + 2 * qd;
                if (col > row0)     s[nj][0] = -1e30f;
                if (col + 1 > row0) s[nj][1] = -1e30f;
                if (col > row0 + 8)     s[nj][2] = -1e30f;
                if (col + 1 > row0 + 8) s[nj][3] = -1e30f;
            }
        }

        float mx0 = -1e30f, mx1 = -1e30f;
        #pragma unroll
        for (int nj = 0; nj < 8; nj++) {
            mx0 = fmaxf(mx0, fmaxf(s[nj][0], s[nj][1]));
            mx1 = fmaxf(mx1, fmaxf(s[nj][2], s[nj][3]));
        }
        mx0 = fmaxf(mx0, __shfl_xor_sync(0xffffffffu, mx0, 1));
        mx0 = fmaxf(mx0, __shfl_xor_sync(0xffffffffu, mx0, 2));
        mx1 = fmaxf(mx1, __shfl_xor_sync(0xffffffffu, mx1, 1));
        mx1 = fmaxf(mx1, __shfl_xor_sync(0xffffffffu, mx1, 2));

        const float mn0 = fmaxf(m0, mx0), mn1 = fmaxf(m1, mx1);
        const float al0 = __expf(m0 - mn0), al1 = __expf(m1 - mn1);
        m0 = mn0; m1 = mn1;

        float rs0 = 0.f, rs1 = 0.f;
        #pragma unroll
        for (int nj = 0; nj < 8; nj++) {
            s[nj][0] = __expf(s[nj][0] - mn0); rs0 += s[nj][0];
            s[nj][1] = __expf(s[nj][1] - mn0); rs0 += s[nj][1];
            s[nj][2] = __expf(s[nj][2] - mn1); rs1 += s[nj][2];
            s[nj][3] = __expf(s[nj][3] - mn1); rs1 += s[nj][3];
        }
        rs0 += __shfl_xor_sync(0xffffffffu, rs0, 1);
        rs0 += __shfl_xor_sync(0xffffffffu, rs0, 2);
        rs1 += __shfl_xor_sync(0xffffffffu, rs1, 1);
        rs1 += __shfl_xor_sync(0xffffffffu, rs1, 2);
        l0 = l0 * al0 + rs0;
        l1 = l1 * al1 + rs1;

        #pragma unroll
        for (int nj = 0; nj < 8; nj++) {
            o[nj][0] *= al0; o[nj][1] *= al0;
            o[nj][2] *= al1; o[nj][3] *= al1;
        }

        #pragma unroll
        for (int ks = 0; ks < 8; ks++) {
            const float p0a = __shfl_sync(0xffffffffu, s[ks][0], srcA);
            const float p0b = __shfl_sync(0xffffffffu, s[ks][1], srcA);
            const float p1a = __shfl_sync(0xffffffffu, s[ks][2], srcA);
            const float p1b = __shfl_sync(0xffffffffu, s[ks][3], srcA);
            const float p2a = __shfl_sync(0xffffffffu, s[ks][0], srcB);
            const float p2b = __shfl_sync(0xffffffffu, s[ks][1], srcB);
            const float p3a = __shfl_sync(0xffffffffu, s[ks][2], srcB);
            const float p3b = __shfl_sync(0xffffffffu, s[ks][3], srcB);
            uint32_t af[4];
            af[0] = f32_to_tf32(e ? p0b : p0a);
            af[1] = f32_to_tf32(e ? p1b : p1a);
            af[2] = f32_to_tf32(e ? p2b : p2a);
            af[3] = f32_to_tf32(e ? p3b : p3a);
            const int kc0 = ks * 8 + qd;
            #pragma unroll
            for (int nj = 0; nj < 8; nj++) {
                mma_tf32(o[nj], af,
                         Vsc[kc0 * VST + nj * 8 + g],
                         Vsc[(kc0 + 4) * VST + nj * 8 + g]);
            }
        }

        if (pref) {
            #pragma unroll
            for (int l = 0; l < 4; l++) {
                const int c = lr[l];
                float2 f0 = __half22float2(*(__half2*)&kreg[l].x);
                float2 f1 = __half22float2(*(__half2*)&kreg[l].y);
                uint4 t;
                t.x = f32_to_tf32(f0.x); t.y = f32_to_tf32(f0.y);
                t.z = f32_to_tf32(f1.x); t.w = f32_to_tf32(f1.y);
                *(uint4*)&Ksn[c * AST + lc] = t;
                f0 = __half22float2(*(__half2*)&vreg[l].x);
                f1 = __half22float2(*(__half2*)&vreg[l].y);
                t.x = f32_to_tf32(f0.x); t.y = f32_to_tf32(f0.y);
                t.z = f32_to_tf32(f1.x); t.w = f32_to_tf32(f1.y);
                *(uint4*)&Vsn[c * VST + lc] = t;
            }
        }
        __syncthreads();
    }

    const float inv0 = 1.f / l0, inv1 = 1.f / l1;
    const int orow = b * NN + row0;
    #pragma unroll
    for (int nj = 0; nj < 8; nj++) {
        const int col = h * DD + nj * 8 + 2 * qd;
        __half2 h0 = __floats2half2_rn(o[nj][0] * inv0, o[nj][1] * inv0);
        __half2 h1 = __floats2half2_rn(o[nj][2] * inv1, o[nj][3] * inv1);
        *(__half2*)(out + (size_t)orow * CC + col) = h0;
        *(__half2*)(out + (size_t)(orow + 8) * CC + col) = h1;
    }
}

// ============================================================================
// Launch
// ============================================================================
extern "C" void kernel_launch(void* const* d_in, const int* in_sizes, int n_in,
                              void* d_out, int out_size)
{
    const float* x      = (const float*)d_in[0];
    // d_in[1] = mask (causal tril, hardcoded in attn kernel)
    const float* qkv_w  = (const float*)d_in[2];
    const float* qkv_b  = (const float*)d_in[3];
    const float* proj_w = (const float*)d_in[4];
    const float* proj_b = (const float*)d_in[5];
    const float* ln1_g  = (const float*)d_in[6];
    const float* ln1_b  = (const float*)d_in[7];
    const float* ln2_g  = (const float*)d_in[8];
    const float* ln2_b  = (const float*)d_in[9];
    const float* w1     = (const float*)d_in[10];
    const float* w2     = (const float*)d_in[11];
    const float* w3     = (const float*)d_in[12];
    float* out = (float*)d_out;

    __half *qkvw_h, *projw_h, *w13_h, *w2_h;
    __half *hh, *qkvh, *attnh, *b1h;
    float* x1;
    cudaGetSymbolAddress((void**)&qkvw_h, g_qkvw_h);
    cudaGetSymbolAddress((void**)&projw_h, g_projw_h);
    cudaGetSymbolAddress((void**)&w13_h, g_w13_h);
    cudaGetSymbolAddress((void**)&w2_h, g_w2_h);
    cudaGetSymbolAddress((void**)&hh,   g_h_h);
    cudaGetSymbolAddress((void**)&qkvh, g_qkv_h);
    cudaGetSymbolAddress((void**)&attnh, g_attn_h);
    cudaGetSymbolAddress((void**)&x1,   g_x1);
    cudaGetSymbolAddress((void**)&b1h,  g_b1_h);

    cudaFuncSetAttribute(attn_kernel,
                         cudaFuncAttributeMaxDynamicSharedMemorySize, ATT_SMEM);
    cudaFuncSetAttribute(gemm_h_kernel,
                         cudaFuncAttributeMaxDynamicSharedMemorySize, GEMM_SMEM);

    // 0. weights -> fp16 (w1/w3 interleaved)
    f2h_kernel<<<(3 * CC * CC) / 1024, 256>>>(qkv_w, qkvw_h);
    f2h_kernel<<<(CC * CC) / 1024, 256>>>(proj_w, projw_h);
    f2h_w13_kernel<<<(FFD * CC) / 1024, 256>>>(w1, w3, w13_h);
    f2h_kernel<<<(CC * FFD) / 1024, 256>>>(w2, w2_h);

    // 1. LN1 (fp16 out)
    ln_kernel<<<MROWS, 256>>>(x, ln1_g, ln1_b, hh);
    // 2. qkv = h @ qkv_w^T + qkv_b -> fp16   [8192, 3072]
    gemm_h_kernel<<<dim3(3 * CC / 128, MROWS / 128), 256, GEMM_SMEM>>>(
        hh, qkvw_h, qkv_b, nullptr, nullptr, qkvh, MROWS, 3 * CC, CC, 0);
    // 3. causal flash attention -> fp16 (R13 tf32 version)
    attn_kernel<<<dim3(NN / 128, BB * HH), 256, ATT_SMEM>>>(qkvh, attnh);
    // 4. x1 = x + attn @ proj_w^T + proj_b -> fp32
    gemm_h_kernel<<<dim3(CC / 128, MROWS / 128), 256, GEMM_SMEM>>>(
        attnh, projw_h, proj_b, x, x1, nullptr, MROWS, CC, CC, 0);
    // 5. LN2 (fp16 out)
    ln_kernel<<<MROWS, 256>>>(x1, ln2_g, ln2_b, hh);
    // 6. b1 = silu(h@w1^T) * (h@w3^T) fused  [8192, 4096] (N=8192 interleaved)
    gemm_h_kernel<<<dim3(2 * FFD / 128, MROWS / 128), 256, GEMM_SMEM>>>(
        hh, w13_h, nullptr, nullptr, nullptr, b1h, MROWS, 2 * FFD, CC, 1);
    // 7. out = x1 + b1 @ w2^T -> fp32        [8192, 1024]
    gemm_h_kernel<<<dim3(CC / 128, MROWS / 128), 256, GEMM_SMEM>>>(
        b1h, w2_h, nullptr, x1, out, nullptr, MROWS, CC, FFD, 0);
}